// round 6
// baseline (speedup 1.0000x reference)
#include <cuda_runtime.h>

// LWTA: groups of 4 consecutive floats, keep first-max, zero others.
// 4096 x 8192 fp32 -> 8,388,608 groups (float4s).
// GPT=8 front-batched plain loads (MLP_p1=8), 256-thread blocks.
// Streaming hints (__ldcs/__stcs) regressed on sm_103a (L1 64%, DRAM 68%) — reverted.

#define GPT 8

__global__ void lwta_kernel(const float4* __restrict__ in,
                            float4* __restrict__ out,
                            int n_groups) {
    int tid = blockIdx.x * blockDim.x + threadIdx.x;
    int stride = gridDim.x * blockDim.x;   // == n_groups / GPT (exact launch)

    // Front-batch all loads: 8 independent LDG.E.128 in flight.
    float4 v[GPT];
#pragma unroll
    for (int j = 0; j < GPT; j++) {
        v[j] = in[tid + j * stride];
    }

#pragma unroll
    for (int j = 0; j < GPT; j++) {
        float4 a = v[j];
        float m = fmaxf(fmaxf(a.x, a.y), fmaxf(a.z, a.w));
        // first-max winner (jnp.argmax tie-break)
        int w = (a.x == m) ? 0 : (a.y == m) ? 1 : (a.z == m) ? 2 : 3;
        float4 o;
        o.x = (w == 0) ? a.x : 0.0f;
        o.y = (w == 1) ? a.y : 0.0f;
        o.z = (w == 2) ? a.z : 0.0f;
        o.w = (w == 3) ? a.w : 0.0f;
        out[tid + j * stride] = o;
    }
}

extern "C" void kernel_launch(void* const* d_in, const int* in_sizes, int n_in,
                              void* d_out, int out_size) {
    const float4* in = (const float4*)d_in[0];
    float4* out = (float4*)d_out;
    int n_groups = in_sizes[0] / 4;        // 8,388,608

    const int threads = 256;
    int total_threads = n_groups / GPT;    // 1,048,576
    int blocks = total_threads / threads;  // 4096
    lwta_kernel<<<blocks, threads>>>(in, out, n_groups);
}

// round 7
// speedup vs baseline: 1.0419x; 1.0419x over previous
#include <cuda_runtime.h>

// LWTA: groups of 4 consecutive floats, keep first-max (jnp.argmax tie-break),
// zero others. 4096 x 8192 fp32.
// 256-bit vector loads/stores (ld/st.global.v8.f32, sm_100+): each thread
// handles 2 x 32B chunks (4 groups), front-batched. Halves LDG/STG count and
// l1tex wavefronts vs the float4 version.

#define VPT 2  // v8 (32B) chunks per thread

__global__ void lwta_kernel(const float* __restrict__ in,
                            float* __restrict__ out) {
    unsigned tid = blockIdx.x * blockDim.x + threadIdx.x;
    unsigned stride = gridDim.x * blockDim.x;

    float r[VPT][8];

    // Front-batch: VPT independent 256-bit loads in flight.
#pragma unroll
    for (int j = 0; j < VPT; j++) {
        const float* p = in + (size_t)(tid + j * stride) * 8;
        asm volatile(
            "ld.global.v8.f32 {%0,%1,%2,%3,%4,%5,%6,%7}, [%8];"
            : "=f"(r[j][0]), "=f"(r[j][1]), "=f"(r[j][2]), "=f"(r[j][3]),
              "=f"(r[j][4]), "=f"(r[j][5]), "=f"(r[j][6]), "=f"(r[j][7])
            : "l"(p));
    }

#pragma unroll
    for (int j = 0; j < VPT; j++) {
#pragma unroll
        for (int g = 0; g < 2; g++) {
            float a0 = r[j][g * 4 + 0];
            float a1 = r[j][g * 4 + 1];
            float a2 = r[j][g * 4 + 2];
            float a3 = r[j][g * 4 + 3];
            float m = fmaxf(fmaxf(a0, a1), fmaxf(a2, a3));
            int w = (a0 == m) ? 0 : (a1 == m) ? 1 : (a2 == m) ? 2 : 3;
            r[j][g * 4 + 0] = (w == 0) ? a0 : 0.0f;
            r[j][g * 4 + 1] = (w == 1) ? a1 : 0.0f;
            r[j][g * 4 + 2] = (w == 2) ? a2 : 0.0f;
            r[j][g * 4 + 3] = (w == 3) ? a3 : 0.0f;
        }
        float* p = out + (size_t)(tid + j * stride) * 8;
        asm volatile(
            "st.global.v8.f32 [%0], {%1,%2,%3,%4,%5,%6,%7,%8};"
            :: "l"(p),
               "f"(r[j][0]), "f"(r[j][1]), "f"(r[j][2]), "f"(r[j][3]),
               "f"(r[j][4]), "f"(r[j][5]), "f"(r[j][6]), "f"(r[j][7])
            : "memory");
    }
}

extern "C" void kernel_launch(void* const* d_in, const int* in_sizes, int n_in,
                              void* d_out, int out_size) {
    const float* in = (const float*)d_in[0];
    float* out = (float*)d_out;
    int n_elems = in_sizes[0];             // 33,554,432
    int n_v8 = n_elems / 8;                // 4,194,304

    const int threads = 256;
    int total_threads = n_v8 / VPT;        // 2,097,152
    int blocks = total_threads / threads;  // 8192
    lwta_kernel<<<blocks, threads>>>(in, out);
}

// round 8
// speedup vs baseline: 1.0442x; 1.0022x over previous
#include <cuda_runtime.h>

// LWTA: groups of 4 consecutive floats, keep first-max (jnp.argmax tie-break),
// zero others. 4096 x 8192 fp32 -> 8,388,608 groups (float4s).
//
// Best-known config (R3): GPT=4 front-batched float4 loads (MLP_p1=4),
// 256-thread blocks, 8192 CTAs, plain LDG.128/STG.128.
// Sweep evidence: GPT=1/8, v8(256-bit), streaming hints all equal-or-worse;
// DRAM plateaus at ~77% = mixed 1:1 R/W HBM stream ceiling (~6.1 TB/s).

#define GPT 4

__global__ void lwta_kernel(const float4* __restrict__ in,
                            float4* __restrict__ out,
                            int n_groups) {
    int tid = blockIdx.x * blockDim.x + threadIdx.x;
    int stride = gridDim.x * blockDim.x;   // == n_groups / GPT (exact launch)

    // Front-batch all loads: 4 independent LDG.E.128 in flight.
    float4 v[GPT];
#pragma unroll
    for (int j = 0; j < GPT; j++) {
        v[j] = in[tid + j * stride];
    }

#pragma unroll
    for (int j = 0; j < GPT; j++) {
        float4 a = v[j];
        float m = fmaxf(fmaxf(a.x, a.y), fmaxf(a.z, a.w));
        // first-max winner (jnp.argmax tie-break)
        int w = (a.x == m) ? 0 : (a.y == m) ? 1 : (a.z == m) ? 2 : 3;
        float4 o;
        o.x = (w == 0) ? a.x : 0.0f;
        o.y = (w == 1) ? a.y : 0.0f;
        o.z = (w == 2) ? a.z : 0.0f;
        o.w = (w == 3) ? a.w : 0.0f;
        out[tid + j * stride] = o;
    }
}

extern "C" void kernel_launch(void* const* d_in, const int* in_sizes, int n_in,
                              void* d_out, int out_size) {
    const float4* in = (const float4*)d_in[0];
    float4* out = (float4*)d_out;
    int n_groups = in_sizes[0] / 4;        // 8,388,608

    const int threads = 256;
    int total_threads = n_groups / GPT;    // 2,097,152
    int blocks = total_threads / threads;  // 8192
    lwta_kernel<<<blocks, threads>>>(in, out, n_groups);
}